// round 6
// baseline (speedup 1.0000x reference)
#include <cuda_runtime.h>
#include <cuda_bf16.h>
#include <cstddef>

#define B_ 32
#define T_ 512
#define H_ 1024
#define G_ 4096
#define NB 128
#define THR 512

__device__ float g_gx[(size_t)B_ * T_ * G_];
__device__ float g_out0[(size_t)B_ * T_ * H_];
__device__ __nv_bfloat16 g_hb[2][2][(size_t)B_ * H_];   // [buf][hi/lo][b*1024+k]
__device__ unsigned g_bar;
__device__ __nv_bfloat16 g_Ahi[(size_t)B_ * T_ * H_];
__device__ __nv_bfloat16 g_Alo[(size_t)B_ * T_ * H_];
__device__ __nv_bfloat16 g_Whi[(size_t)G_ * H_];
__device__ __nv_bfloat16 g_Wlo[(size_t)G_ * H_];

// ---------------- hi/lo bf16 split conversion ---------------------------------
__global__ __launch_bounds__(256) void conv_split(
    const float* __restrict__ s, __nv_bfloat16* __restrict__ hi,
    __nv_bfloat16* __restrict__ lo, int n4)
{
    int i = blockIdx.x * 256 + threadIdx.x;
    if (i >= n4) return;
    float4 v = ((const float4*)s)[i];
    __nv_bfloat16 h0 = __float2bfloat16(v.x), h1 = __float2bfloat16(v.y);
    __nv_bfloat16 h2 = __float2bfloat16(v.z), h3 = __float2bfloat16(v.w);
    __nv_bfloat16 l0 = __float2bfloat16(v.x - __bfloat162float(h0));
    __nv_bfloat16 l1 = __float2bfloat16(v.y - __bfloat162float(h1));
    __nv_bfloat16 l2 = __float2bfloat16(v.z - __bfloat162float(h2));
    __nv_bfloat16 l3 = __float2bfloat16(v.w - __bfloat162float(h3));
    ((__nv_bfloat162*)hi)[i * 2]     = __nv_bfloat162(h0, h1);
    ((__nv_bfloat162*)hi)[i * 2 + 1] = __nv_bfloat162(h2, h3);
    ((__nv_bfloat162*)lo)[i * 2]     = __nv_bfloat162(l0, l1);
    ((__nv_bfloat162*)lo)[i * 2 + 1] = __nv_bfloat162(l2, l3);
}

// ---------------- mma helpers --------------------------------------------------
__device__ __forceinline__ void ldsm4(unsigned* r, unsigned a) {
    asm volatile("ldmatrix.sync.aligned.m8n8.x4.shared.b16 {%0,%1,%2,%3}, [%4];"
                 : "=r"(r[0]), "=r"(r[1]), "=r"(r[2]), "=r"(r[3]) : "r"(a));
}
__device__ __forceinline__ void mma16816(float* c, const unsigned* a,
                                         unsigned b0, unsigned b1) {
    asm volatile(
        "mma.sync.aligned.m16n8k16.row.col.f32.bf16.bf16.f32 "
        "{%0,%1,%2,%3}, {%4,%5,%6,%7}, {%8,%9}, {%0,%1,%2,%3};"
        : "+f"(c[0]), "+f"(c[1]), "+f"(c[2]), "+f"(c[3])
        : "r"(a[0]), "r"(a[1]), "r"(a[2]), "r"(a[3]), "r"(b0), "r"(b1));
}
__device__ __forceinline__ void cpa(unsigned s, const void* g) {
    asm volatile("cp.async.cg.shared.global [%0], [%1], 16;" :: "r"(s), "l"(g));
}

// ---------------- tensor-core GEMM (unchanged from R5) ------------------------
#define SR 40
#define BUFB (128 * SR * 2)
#define OFF_AH 0
#define OFF_AL (2 * BUFB)
#define OFF_BH (4 * BUFB)
#define OFF_BL (6 * BUFB)
#define TC_SMEM (8 * BUFB)

__global__ __launch_bounds__(256, 1) void tc_gemm(
    const __nv_bfloat16* __restrict__ Ahi, const __nv_bfloat16* __restrict__ Alo,
    const __nv_bfloat16* __restrict__ Whi, const __nv_bfloat16* __restrict__ Wlo,
    const float* __restrict__ bias)
{
    extern __shared__ char sm[];
    const unsigned sbase = (unsigned)__cvta_generic_to_shared(sm);
    const int tid = threadIdx.x, lane = tid & 31, wid = tid >> 5;
    const int wm = wid & 3, wn = wid >> 2;
    const int m0 = blockIdx.y * 128, n0 = blockIdx.x * 128;

    int frow[2], fch[2];
    unsigned sA[2];
#pragma unroll
    for (int u = 0; u < 2; ++u) {
        int id = tid + 256 * u;
        frow[u] = id >> 2; fch[u] = (id & 3) * 8;
        sA[u] = (frow[u] * SR + fch[u]) * 2;
    }
    const int arow = wm * 32 + (lane & 7) + (lane & 8);
    const unsigned a_base = (arow * SR + (lane >> 4) * 8) * 2;
    const int brow = wn * 64 + (lane & 7) + (lane >> 4) * 8;
    const unsigned b_base = (brow * SR + ((lane >> 3) & 1) * 8) * 2;

    float c[2][8][4];
#pragma unroll
    for (int i = 0; i < 2; ++i)
#pragma unroll
        for (int j = 0; j < 8; ++j)
#pragma unroll
            for (int q = 0; q < 4; ++q) c[i][j][q] = 0.f;

#pragma unroll
    for (int u = 0; u < 2; ++u) {
        size_t ga = (size_t)(m0 + frow[u]) * H_ + fch[u];
        size_t gb = (size_t)(n0 + frow[u]) * H_ + fch[u];
        cpa(sbase + OFF_AH + sA[u], &Ahi[ga]);
        cpa(sbase + OFF_AL + sA[u], &Alo[ga]);
        cpa(sbase + OFF_BH + sA[u], &Whi[gb]);
        cpa(sbase + OFF_BL + sA[u], &Wlo[gb]);
    }
    asm volatile("cp.async.commit_group;");

    for (int s = 0; s < 32; ++s) {
        asm volatile("cp.async.wait_group 0;");
        __syncthreads();
        if (s + 1 < 32) {
            int k0 = (s + 1) * 32, bf = (s + 1) & 1;
#pragma unroll
            for (int u = 0; u < 2; ++u) {
                size_t ga = (size_t)(m0 + frow[u]) * H_ + k0 + fch[u];
                size_t gb = (size_t)(n0 + frow[u]) * H_ + k0 + fch[u];
                cpa(sbase + OFF_AH + bf * BUFB + sA[u], &Ahi[ga]);
                cpa(sbase + OFF_AL + bf * BUFB + sA[u], &Alo[ga]);
                cpa(sbase + OFF_BH + bf * BUFB + sA[u], &Whi[gb]);
                cpa(sbase + OFF_BL + bf * BUFB + sA[u], &Wlo[gb]);
            }
            asm volatile("cp.async.commit_group;");
        }
        const unsigned bo = (s & 1) * BUFB;
#pragma unroll
        for (int kk = 0; kk < 2; ++kk) {
            unsigned ah[2][4], al[2][4], bh[4][4], bl[4][4];
#pragma unroll
            for (int mi = 0; mi < 2; ++mi) {
                unsigned ad = sbase + bo + a_base + mi * (16 * SR * 2) + kk * 32;
                ldsm4(ah[mi], ad + OFF_AH);
                ldsm4(al[mi], ad + OFF_AL);
            }
#pragma unroll
            for (int j = 0; j < 4; ++j) {
                unsigned bd = sbase + bo + b_base + j * (16 * SR * 2) + kk * 32;
                ldsm4(bh[j], bd + OFF_BH);
                ldsm4(bl[j], bd + OFF_BL);
            }
#pragma unroll
            for (int mi = 0; mi < 2; ++mi)
#pragma unroll
                for (int j = 0; j < 4; ++j) {
                    mma16816(c[mi][2*j],   ah[mi], bh[j][0], bh[j][1]);
                    mma16816(c[mi][2*j+1], ah[mi], bh[j][2], bh[j][3]);
                    mma16816(c[mi][2*j],   ah[mi], bl[j][0], bl[j][1]);
                    mma16816(c[mi][2*j+1], ah[mi], bl[j][2], bl[j][3]);
                    mma16816(c[mi][2*j],   al[mi], bh[j][0], bh[j][1]);
                    mma16816(c[mi][2*j+1], al[mi], bh[j][2], bh[j][3]);
                }
        }
        __syncthreads();
    }
#pragma unroll
    for (int mi = 0; mi < 2; ++mi) {
        int gr = m0 + wm * 32 + mi * 16 + (lane >> 2);
#pragma unroll
        for (int ni = 0; ni < 8; ++ni) {
            int gc = n0 + wn * 64 + ni * 8 + (lane & 3) * 2;
            float2 bv = *(const float2*)&bias[gc];
            float* cc = c[mi][ni];
            *(float2*)&g_gx[(size_t)gr * G_ + gc] =
                make_float2(cc[0] + bv.x, cc[1] + bv.y);
            *(float2*)&g_gx[(size_t)(gr + 8) * G_ + gc] =
                make_float2(cc[2] + bv.x, cc[3] + bv.y);
        }
    }
}

// ---------------- persistent tensorized LSTM recurrence (R6) ------------------
__device__ __forceinline__ float sigf(float x) { return 1.0f / (1.0f + __expf(-x)); }

__device__ __forceinline__ void grid_bar(unsigned want) {
    __syncthreads();
    if (threadIdx.x == 0) {
        __threadfence();
        atomicAdd(&g_bar, 1u);
        unsigned v;
        do { asm volatile("ld.acquire.gpu.u32 %0, [%1];" : "=r"(v) : "l"(&g_bar)); }
        while (v < want);
    }
    __syncthreads();
}

// SMEM map (bytes):
//  [0, 66048)            Wlo  [32 rows][1032] bf16
//  [66048, 197120)       H    [2 planes][32 b][2048B swizzled]  (overlay: Whi temp, partials)
//  [197120, 201728)      g_s  [32][36] f32
//  [201728, 201856)      len
#define WLS 1032
#define OFF_WLO 0
#define OFF_H   66048
#define PLSZ    65536
#define OFF_GS  197120
#define OFF_LEN 201728
#define REC_SMEM 201856
#define PRS 34                     // partial row stride (f32)

__global__ __launch_bounds__(THR, 1) void lstm_rec(
    const float* __restrict__ whh, const void* __restrict__ len_raw,
    float* __restrict__ outp, float* __restrict__ cdst, float* __restrict__ hdst)
{
    extern __shared__ char sm[];
    const unsigned sbase = (unsigned)__cvta_generic_to_shared(sm);
    float* part = (float*)(sm + OFF_H);        // overlay after mma
    float* g_s  = (float*)(sm + OFF_GS);
    int* len_s  = (int*)(sm + OFF_LEN);

    const int tid = threadIdx.x, lane = tid & 31, wid = tid >> 5;
    const int j0 = blockIdx.x * 8;
    const int kw = wid & 7, mh = wid >> 3;

    if (tid == 0) {
        const int* L = (const int*)len_raw;
        bool is64 = true;
        for (int i = 1; i < 32; i += 2) if (L[i] != 0) { is64 = false; break; }
        for (int b = 0; b < 32; ++b) len_s[b] = is64 ? L[2 * b] : L[b];
    }

    // ---- stage W slice: Whi -> H temp (swizzled, stride 2048B), Wlo -> SMEM ----
    {
        const int r = tid & 31;                       // smem gate row
        const int grow = (r >> 3) * 1024 + j0 + (r & 7);
        const int k0 = (tid >> 5) * 64;               // 64 elems per thread
        const float* src = &whh[(size_t)grow * H_ + k0];
        const unsigned xw = (r & 7) << 4;
        __nv_bfloat162* wlo = (__nv_bfloat162*)(sm + OFF_WLO);
#pragma unroll
        for (int kk = 0; kk < 64; kk += 4) {
            float4 v = *(const float4*)&src[kk];
            __nv_bfloat16 h0 = __float2bfloat16(v.x), h1 = __float2bfloat16(v.y);
            __nv_bfloat16 h2 = __float2bfloat16(v.z), h3 = __float2bfloat16(v.w);
            int kb = (k0 + kk) * 2;                   // byte col
            *(__nv_bfloat162*)(sm + OFF_H + r * 2048 + ((kb) ^ xw)) =
                __nv_bfloat162(h0, h1);
            *(__nv_bfloat162*)(sm + OFF_H + r * 2048 + ((kb + 4) ^ xw)) =
                __nv_bfloat162(h2, h3);
            int e = r * WLS + k0 + kk;
            wlo[e / 2]     = __nv_bfloat162(__float2bfloat16(v.x - __bfloat162float(h0)),
                                            __float2bfloat16(v.y - __bfloat162float(h1)));
            wlo[e / 2 + 1] = __nv_bfloat162(__float2bfloat16(v.z - __bfloat162float(h2)),
                                            __float2bfloat16(v.w - __bfloat162float(h3)));
        }
    }
    __syncthreads();

    // ---- load Whi fragments into registers (persist across all steps) --------
    const int amr = mh * 16 + (lane & 7) + (lane & 8);    // A row
    const unsigned xa = (amr & 7) << 4;
    unsigned wa[8][4];
#pragma unroll
    for (int kt = 0; kt < 8; ++kt) {
        unsigned col = (unsigned)((kw * 128 + kt * 16 + (lane >> 4) * 8) * 2);
        ldsm4(wa[kt], sbase + OFF_H + amr * 2048 + (col ^ xa));
    }
    // Wlo ldsm base (stride 1032, no swizzle)
    const unsigned alo_base = sbase + OFF_WLO +
        (unsigned)((amr * WLS + kw * 128 + (lane >> 4) * 8) * 2);

    // B (h) ldsm bases
    const int br0 = (lane & 7) + (lane >> 4) * 8;         // n rows 0..15
    const unsigned xb = (br0 & 7) << 4;
    const unsigned bk4 = ((lane >> 3) & 1) * 16;          // byte bit4
    const unsigned bbase0 = sbase + OFF_H + br0 * 2048 + kw * 256;
    const unsigned bbase1 = bbase0 + 16 * 2048;

    // staging map: thread -> (plane, batch, 16B-unit stream)
    const int spl = tid >> 8, sr = tid & 255, sb = sr & 31, s8 = sr >> 5;
    const unsigned sx = ((unsigned)(s8 * 16)) ^ ((sb & 7) << 4);
    char* sdst = sm + OFF_H + spl * PLSZ + sb * 2048 + sx;

    // reduce map
    const int rrow = tid >> 4, rb = (tid & 15) * 2;
    const size_t gxcol = (size_t)(rrow >> 3) * 1024 + j0 + (rrow & 7);

    // update map
    const int ju = tid & 7, bu = tid >> 3;
    float c_reg = 0.f, h_reg = 0.f;
    if (tid < 256) {
        g_hb[0][0][bu * H_ + j0 + ju] = __float2bfloat16(0.f);
        g_hb[0][1][bu * H_ + j0 + ju] = __float2bfloat16(0.f);
    }

    unsigned want = NB;
    grid_bar(want);

    for (int t = 0; t < T_; ++t) {
        // gx prefetch
        float gx0 = __ldg(&g_gx[((size_t)rb * T_ + t) * G_ + gxcol]);
        float gx1 = __ldg(&g_gx[((size_t)(rb + 1) * T_ + t) * G_ + gxcol]);

        // stage full h (hi+lo) into SMEM, swizzled
        const __nv_bfloat16* hsrc = g_hb[t & 1][spl] + sb * 1024 + s8 * 8;
#pragma unroll
        for (int jb = 0; jb < 4; ++jb) {
            uint4 v[4];
#pragma unroll
            for (int u = 0; u < 4; ++u)
                v[u] = __ldcg((const uint4*)(hsrc + (jb * 4 + u) * 64));
#pragma unroll
            for (int u = 0; u < 4; ++u)
                *(uint4*)(sdst + (jb * 4 + u) * 128) = v[u];
        }
        __syncthreads();

        // mma: c[4 n-tiles][4]
        float c[4][4];
#pragma unroll
        for (int n = 0; n < 4; ++n)
#pragma unroll
            for (int q = 0; q < 4; ++q) c[n][q] = 0.f;

#pragma unroll
        for (int kt = 0; kt < 8; ++kt) {
            const unsigned colb = ((unsigned)(kt * 32) + bk4) ^ xb;
            unsigned bh0[4], bh1[4], bl0[4], bl1[4], al[4];
            ldsm4(bh0, bbase0 + colb);
            ldsm4(bh1, bbase1 + colb);
            ldsm4(bl0, bbase0 + PLSZ + colb);
            ldsm4(bl1, bbase1 + PLSZ + colb);
            ldsm4(al, alo_base + kt * 32);
            mma16816(c[0], wa[kt], bh0[0], bh0[1]);
            mma16816(c[1], wa[kt], bh0[2], bh0[3]);
            mma16816(c[2], wa[kt], bh1[0], bh1[1]);
            mma16816(c[3], wa[kt], bh1[2], bh1[3]);
            mma16816(c[0], wa[kt], bl0[0], bl0[1]);
            mma16816(c[1], wa[kt], bl0[2], bl0[3]);
            mma16816(c[2], wa[kt], bl1[0], bl1[1]);
            mma16816(c[3], wa[kt], bl1[2], bl1[3]);
            mma16816(c[0], al, bh0[0], bh0[1]);
            mma16816(c[1], al, bh0[2], bh0[3]);
            mma16816(c[2], al, bh1[0], bh1[1]);
            mma16816(c[3], al, bh1[2], bh1[3]);
        }
        __syncthreads();                 // h fully consumed -> overlay partials

#pragma unroll
        for (int n = 0; n < 4; ++n) {
            int m = mh * 16 + (lane >> 2);
            int nn = n * 8 + (lane & 3) * 2;
            *(float2*)&part[(kw * 32 + m) * PRS + nn]     = make_float2(c[n][0], c[n][1]);
            *(float2*)&part[(kw * 32 + m + 8) * PRS + nn] = make_float2(c[n][2], c[n][3]);
        }
        __syncthreads();

        // reduce over kw + gx
        {
            float2 s = *(float2*)&part[rrow * PRS + rb];
#pragma unroll
            for (int k = 1; k < 8; ++k) {
                float2 p = *(float2*)&part[(k * 32 + rrow) * PRS + rb];
                s.x += p.x; s.y += p.y;
            }
            g_s[rrow * 36 + rb]     = s.x + gx0;
            g_s[rrow * 36 + rb + 1] = s.y + gx1;
        }
        __syncthreads();

        // pointwise update (fp32 state), threads 0..255
        if (tid < 256) {
            float fg = sigf(g_s[(0 * 8 + ju) * 36 + bu]);
            float ig = sigf(g_s[(1 * 8 + ju) * 36 + bu]);
            float og = sigf(g_s[(2 * 8 + ju) * 36 + bu]);
            float cg = tanhf(g_s[(3 * 8 + ju) * 36 + bu]);
            float cn = fg * c_reg + ig * cg;
            float hn = og * tanhf(cn);
            if (t < len_s[bu]) { c_reg = cn; h_reg = hn; }
            __nv_bfloat16 hh = __float2bfloat16(h_reg);
            __nv_bfloat16 hl = __float2bfloat16(h_reg - __bfloat162float(hh));
            int nbuf = (t & 1) ^ 1;
            g_hb[nbuf][0][bu * H_ + j0 + ju] = hh;
            g_hb[nbuf][1][bu * H_ + j0 + ju] = hl;
            outp[((size_t)bu * T_ + t) * H_ + (j0 + ju)] = h_reg;
        }

        want += NB;
        grid_bar(want);
    }
    if (tid < 256) {
        cdst[(size_t)bu * H_ + j0 + ju] = c_reg;
        hdst[(size_t)bu * H_ + j0 + ju] = h_reg;
    }
}

extern "C" void kernel_launch(void* const* d_in, const int* in_sizes, int n_in,
                              void* d_out, int out_size)
{
    const float* x    = (const float*)d_in[0];
    const void*  len  = d_in[1];
    const float* wih0 = (const float*)d_in[2];
    const float* whh0 = (const float*)d_in[3];
    const float* b0   = (const float*)d_in[4];
    const float* wih1 = (const float*)d_in[5];
    const float* whh1 = (const float*)d_in[6];
    const float* b1   = (const float*)d_in[7];
    float* out = (float*)d_out;

    void *bar_p, *out0_p, *ahi_p, *alo_p, *whi_p, *wlo_p;
    cudaGetSymbolAddress(&bar_p, g_bar);
    cudaGetSymbolAddress(&out0_p, g_out0);
    cudaGetSymbolAddress(&ahi_p, g_Ahi);
    cudaGetSymbolAddress(&alo_p, g_Alo);
    cudaGetSymbolAddress(&whi_p, g_Whi);
    cudaGetSymbolAddress(&wlo_p, g_Wlo);
    float* out0 = (float*)out0_p;
    __nv_bfloat16* Ahi = (__nv_bfloat16*)ahi_p;
    __nv_bfloat16* Alo = (__nv_bfloat16*)alo_p;
    __nv_bfloat16* Whi = (__nv_bfloat16*)whi_p;
    __nv_bfloat16* Wlo = (__nv_bfloat16*)wlo_p;

    cudaFuncSetAttribute(lstm_rec, cudaFuncAttributeMaxDynamicSharedMemorySize, REC_SMEM);
    cudaFuncSetAttribute(tc_gemm, cudaFuncAttributeMaxDynamicSharedMemorySize, TC_SMEM);

    const size_t O1 = (size_t)B_ * T_ * H_;
    float* c0dst = out + O1;
    float* c1dst = out + O1 + (size_t)B_ * H_;
    float* h0dst = out + O1 + 2 * (size_t)B_ * H_;
    float* h1dst = out + O1 + 3 * (size_t)B_ * H_;

    const int nA4 = (B_ * T_ * H_) / 4;
    const int nW4 = (G_ * H_) / 4;
    dim3 gg(G_ / 128, (B_ * T_) / 128);

    conv_split<<<nW4 / 256, 256>>>(wih0, Whi, Wlo, nW4);
    conv_split<<<nA4 / 256, 256>>>(x, Ahi, Alo, nA4);
    tc_gemm<<<gg, 256, TC_SMEM>>>(Ahi, Alo, Whi, Wlo, b0);
    cudaMemsetAsync(bar_p, 0, sizeof(unsigned), 0);
    lstm_rec<<<NB, THR, REC_SMEM>>>(whh0, len, out0, c0dst, h0dst);

    conv_split<<<nW4 / 256, 256>>>(wih1, Whi, Wlo, nW4);
    conv_split<<<nA4 / 256, 256>>>(out0, Ahi, Alo, nA4);
    tc_gemm<<<gg, 256, TC_SMEM>>>(Ahi, Alo, Whi, Wlo, b1);
    cudaMemsetAsync(bar_p, 0, sizeof(unsigned), 0);
    lstm_rec<<<NB, THR, REC_SMEM>>>(whh1, len, out, c1dst, h1dst);
}

// round 7
// speedup vs baseline: 1.1356x; 1.1356x over previous
#include <cuda_runtime.h>
#include <cuda_bf16.h>
#include <cstddef>

#define B_ 32
#define T_ 512
#define H_ 1024
#define G_ 4096
#define NB 128
#define THR 512

__device__ float g_gx[(size_t)B_ * T_ * G_];
__device__ float g_out0[(size_t)B_ * T_ * H_];
__device__ __nv_bfloat16 g_hb[2][2][(size_t)B_ * H_];   // [buf][hi/lo][b*1024+k]
__device__ unsigned g_bar;
__device__ __nv_bfloat16 g_Ahi[(size_t)B_ * T_ * H_];
__device__ __nv_bfloat16 g_Alo[(size_t)B_ * T_ * H_];
__device__ __nv_bfloat16 g_Whi[(size_t)G_ * H_];
__device__ __nv_bfloat16 g_Wlo[(size_t)G_ * H_];

// ---------------- hi/lo bf16 split conversion ---------------------------------
__global__ __launch_bounds__(256) void conv_split(
    const float* __restrict__ s, __nv_bfloat16* __restrict__ hi,
    __nv_bfloat16* __restrict__ lo, int n4)
{
    int i = blockIdx.x * 256 + threadIdx.x;
    if (i >= n4) return;
    float4 v = ((const float4*)s)[i];
    __nv_bfloat16 h0 = __float2bfloat16(v.x), h1 = __float2bfloat16(v.y);
    __nv_bfloat16 h2 = __float2bfloat16(v.z), h3 = __float2bfloat16(v.w);
    __nv_bfloat16 l0 = __float2bfloat16(v.x - __bfloat162float(h0));
    __nv_bfloat16 l1 = __float2bfloat16(v.y - __bfloat162float(h1));
    __nv_bfloat16 l2 = __float2bfloat16(v.z - __bfloat162float(h2));
    __nv_bfloat16 l3 = __float2bfloat16(v.w - __bfloat162float(h3));
    ((__nv_bfloat162*)hi)[i * 2]     = __nv_bfloat162(h0, h1);
    ((__nv_bfloat162*)hi)[i * 2 + 1] = __nv_bfloat162(h2, h3);
    ((__nv_bfloat162*)lo)[i * 2]     = __nv_bfloat162(l0, l1);
    ((__nv_bfloat162*)lo)[i * 2 + 1] = __nv_bfloat162(l2, l3);
}

// ---------------- mma helpers --------------------------------------------------
__device__ __forceinline__ void ldsm4(unsigned* r, unsigned a) {
    asm volatile("ldmatrix.sync.aligned.m8n8.x4.shared.b16 {%0,%1,%2,%3}, [%4];"
                 : "=r"(r[0]), "=r"(r[1]), "=r"(r[2]), "=r"(r[3]) : "r"(a));
}
__device__ __forceinline__ void mma16816(float* c, const unsigned* a,
                                         unsigned b0, unsigned b1) {
    asm volatile(
        "mma.sync.aligned.m16n8k16.row.col.f32.bf16.bf16.f32 "
        "{%0,%1,%2,%3}, {%4,%5,%6,%7}, {%8,%9}, {%0,%1,%2,%3};"
        : "+f"(c[0]), "+f"(c[1]), "+f"(c[2]), "+f"(c[3])
        : "r"(a[0]), "r"(a[1]), "r"(a[2]), "r"(a[3]), "r"(b0), "r"(b1));
}
__device__ __forceinline__ void cpa(unsigned s, const void* g) {
    asm volatile("cp.async.cg.shared.global [%0], [%1], 16;" :: "r"(s), "l"(g));
}

// ---------------- tensor-core GEMM (unchanged from R5) ------------------------
#define SR 40
#define BUFB (128 * SR * 2)
#define OFF_AH 0
#define OFF_AL (2 * BUFB)
#define OFF_BH (4 * BUFB)
#define OFF_BL (6 * BUFB)
#define TC_SMEM (8 * BUFB)

__global__ __launch_bounds__(256, 1) void tc_gemm(
    const __nv_bfloat16* __restrict__ Ahi, const __nv_bfloat16* __restrict__ Alo,
    const __nv_bfloat16* __restrict__ Whi, const __nv_bfloat16* __restrict__ Wlo,
    const float* __restrict__ bias)
{
    extern __shared__ char sm[];
    const unsigned sbase = (unsigned)__cvta_generic_to_shared(sm);
    const int tid = threadIdx.x, lane = tid & 31, wid = tid >> 5;
    const int wm = wid & 3, wn = wid >> 2;
    const int m0 = blockIdx.y * 128, n0 = blockIdx.x * 128;

    int frow[2], fch[2];
    unsigned sA[2];
#pragma unroll
    for (int u = 0; u < 2; ++u) {
        int id = tid + 256 * u;
        frow[u] = id >> 2; fch[u] = (id & 3) * 8;
        sA[u] = (frow[u] * SR + fch[u]) * 2;
    }
    const int arow = wm * 32 + (lane & 7) + (lane & 8);
    const unsigned a_base = (arow * SR + (lane >> 4) * 8) * 2;
    const int brow = wn * 64 + (lane & 7) + (lane >> 4) * 8;
    const unsigned b_base = (brow * SR + ((lane >> 3) & 1) * 8) * 2;

    float c[2][8][4];
#pragma unroll
    for (int i = 0; i < 2; ++i)
#pragma unroll
        for (int j = 0; j < 8; ++j)
#pragma unroll
            for (int q = 0; q < 4; ++q) c[i][j][q] = 0.f;

#pragma unroll
    for (int u = 0; u < 2; ++u) {
        size_t ga = (size_t)(m0 + frow[u]) * H_ + fch[u];
        size_t gb = (size_t)(n0 + frow[u]) * H_ + fch[u];
        cpa(sbase + OFF_AH + sA[u], &Ahi[ga]);
        cpa(sbase + OFF_AL + sA[u], &Alo[ga]);
        cpa(sbase + OFF_BH + sA[u], &Whi[gb]);
        cpa(sbase + OFF_BL + sA[u], &Wlo[gb]);
    }
    asm volatile("cp.async.commit_group;");

    for (int s = 0; s < 32; ++s) {
        asm volatile("cp.async.wait_group 0;");
        __syncthreads();
        if (s + 1 < 32) {
            int k0 = (s + 1) * 32, bf = (s + 1) & 1;
#pragma unroll
            for (int u = 0; u < 2; ++u) {
                size_t ga = (size_t)(m0 + frow[u]) * H_ + k0 + fch[u];
                size_t gb = (size_t)(n0 + frow[u]) * H_ + k0 + fch[u];
                cpa(sbase + OFF_AH + bf * BUFB + sA[u], &Ahi[ga]);
                cpa(sbase + OFF_AL + bf * BUFB + sA[u], &Alo[ga]);
                cpa(sbase + OFF_BH + bf * BUFB + sA[u], &Whi[gb]);
                cpa(sbase + OFF_BL + bf * BUFB + sA[u], &Wlo[gb]);
            }
            asm volatile("cp.async.commit_group;");
        }
        const unsigned bo = (s & 1) * BUFB;
#pragma unroll
        for (int kk = 0; kk < 2; ++kk) {
            unsigned ah[2][4], al[2][4], bh[4][4], bl[4][4];
#pragma unroll
            for (int mi = 0; mi < 2; ++mi) {
                unsigned ad = sbase + bo + a_base + mi * (16 * SR * 2) + kk * 32;
                ldsm4(ah[mi], ad + OFF_AH);
                ldsm4(al[mi], ad + OFF_AL);
            }
#pragma unroll
            for (int j = 0; j < 4; ++j) {
                unsigned bd = sbase + bo + b_base + j * (16 * SR * 2) + kk * 32;
                ldsm4(bh[j], bd + OFF_BH);
                ldsm4(bl[j], bd + OFF_BL);
            }
#pragma unroll
            for (int mi = 0; mi < 2; ++mi)
#pragma unroll
                for (int j = 0; j < 4; ++j) {
                    mma16816(c[mi][2*j],   ah[mi], bh[j][0], bh[j][1]);
                    mma16816(c[mi][2*j+1], ah[mi], bh[j][2], bh[j][3]);
                    mma16816(c[mi][2*j],   ah[mi], bl[j][0], bl[j][1]);
                    mma16816(c[mi][2*j+1], ah[mi], bl[j][2], bl[j][3]);
                    mma16816(c[mi][2*j],   al[mi], bh[j][0], bh[j][1]);
                    mma16816(c[mi][2*j+1], al[mi], bh[j][2], bh[j][3]);
                }
        }
        __syncthreads();
    }
#pragma unroll
    for (int mi = 0; mi < 2; ++mi) {
        int gr = m0 + wm * 32 + mi * 16 + (lane >> 2);
#pragma unroll
        for (int ni = 0; ni < 8; ++ni) {
            int gc = n0 + wn * 64 + ni * 8 + (lane & 3) * 2;
            float2 bv = *(const float2*)&bias[gc];
            float* cc = c[mi][ni];
            *(float2*)&g_gx[(size_t)gr * G_ + gc] =
                make_float2(cc[0] + bv.x, cc[1] + bv.y);
            *(float2*)&g_gx[(size_t)(gr + 8) * G_ + gc] =
                make_float2(cc[2] + bv.x, cc[3] + bv.y);
        }
    }
}

// ---------------- persistent tensorized LSTM recurrence (R7) ------------------
__device__ __forceinline__ float sigf(float x) { return 1.0f / (1.0f + __expf(-x)); }

__device__ __forceinline__ void grid_bar(unsigned want) {
    __syncthreads();
    if (threadIdx.x == 0) {
        __threadfence();
        atomicAdd(&g_bar, 1u);
        unsigned v;
        do { asm volatile("ld.acquire.gpu.u32 %0, [%1];" : "=r"(v) : "l"(&g_bar)); }
        while (v < want);
    }
    __syncthreads();
}

// SMEM map (bytes):
//  [0, 65536)        Alo  [32 m][2048B] xor-swizzled
//  [65536, 196608)   H    [8 chunks][2 planes][32 b][256B] (init: Whi temp; per-step: partials overlay)
//  [196608, 200960)  g_s  [32][34] f32
//  [200960, 201088)  len
#define OFF_ALO 0
#define OFF_H   65536
#define CHK     16384
#define OFF_GS  196608
#define OFF_LEN 200960
#define REC_SMEM 201088

__global__ __launch_bounds__(THR, 1) void lstm_rec(
    const float* __restrict__ whh, const void* __restrict__ len_raw,
    float* __restrict__ outp, float* __restrict__ cdst, float* __restrict__ hdst)
{
    extern __shared__ char sm[];
    const unsigned sbase = (unsigned)__cvta_generic_to_shared(sm);
    float* g_s = (float*)(sm + OFF_GS);
    int* len_s = (int*)(sm + OFF_LEN);

    const int tid = threadIdx.x, lane = tid & 31, wid = tid >> 5;
    const int j0 = blockIdx.x * 8;
    const int kw = wid >> 1, nh = wid & 1;       // 8 k-slices x 2 n-halves

    if (tid == 0) {
        const int* L = (const int*)len_raw;
        bool is64 = true;
        for (int i = 1; i < 32; i += 2) if (L[i] != 0) { is64 = false; break; }
        for (int b = 0; b < 32; ++b) len_s[b] = is64 ? L[2 * b] : L[b];
    }

    // ---- stage Whi -> H temp, Wlo -> Alo region (rows stride 2048B, xor swz) --
    {
        const int r = tid & 31;
        const int grow = (r >> 3) * 1024 + j0 + (r & 7);
        const int k0 = (tid >> 5) * 64;
        const float* src = &whh[(size_t)grow * H_ + k0];
        const unsigned xw = (r & 7) << 4;
#pragma unroll
        for (int kk = 0; kk < 64; kk += 4) {
            float4 v = *(const float4*)&src[kk];
            __nv_bfloat16 h0 = __float2bfloat16(v.x), h1 = __float2bfloat16(v.y);
            __nv_bfloat16 h2 = __float2bfloat16(v.z), h3 = __float2bfloat16(v.w);
            int kb = (k0 + kk) * 2;
            *(__nv_bfloat162*)(sm + OFF_H + r * 2048 + (kb ^ xw)) = __nv_bfloat162(h0, h1);
            *(__nv_bfloat162*)(sm + OFF_H + r * 2048 + ((kb + 4) ^ xw)) = __nv_bfloat162(h2, h3);
            *(__nv_bfloat162*)(sm + OFF_ALO + r * 2048 + (kb ^ xw)) =
                __nv_bfloat162(__float2bfloat16(v.x - __bfloat162float(h0)),
                               __float2bfloat16(v.y - __bfloat162float(h1)));
            *(__nv_bfloat162*)(sm + OFF_ALO + r * 2048 + ((kb + 4) ^ xw)) =
                __nv_bfloat162(__float2bfloat16(v.z - __bfloat162float(h2)),
                               __float2bfloat16(v.w - __bfloat162float(h3)));
        }
    }
    __syncthreads();

    // ---- Whi fragments -> registers (persist across all steps) ---------------
    const unsigned xa = (lane & 7) << 4;
    unsigned arow[2];
#pragma unroll
    for (int mi = 0; mi < 2; ++mi)
        arow[mi] = (unsigned)((mi * 16 + (lane & 7) + (lane & 8)) * 2048);
    const unsigned acolk = (unsigned)((kw * 128 + (lane >> 4) * 8) * 2);

    unsigned wa[8][2][4];
#pragma unroll
    for (int kt = 0; kt < 8; ++kt)
#pragma unroll
        for (int mi = 0; mi < 2; ++mi)
            ldsm4(wa[kt][mi], sbase + OFF_H + arow[mi] + ((acolk + kt * 32) ^ xa));
    __syncthreads();

    // B addressing (per-chunk region)
    const int bb = nh * 16 + (lane & 7) + (lane >> 4) * 8;   // batch row 0..31
    const unsigned xb = (bb & 15) << 4;
    const unsigned bk4 = ((lane >> 3) & 1) * 16;
    const unsigned bbase = sbase + OFF_H + kw * CHK + bb * 256;

    // staging: warp-pair kw stages its chunk; plane = nh, b = lane
    char* sdst = sm + OFF_H + kw * CHK + nh * 8192 + lane * 256;
    const unsigned sx = (lane & 15) << 4;

    // reduce map
    const int rm = tid >> 4, rn = (tid & 15) * 2;
    const size_t gxcol = (size_t)(rm >> 3) * 1024 + j0 + (rm & 7);

    // update map
    const int ju = tid & 7, bu = tid >> 3;
    float c_reg = 0.f, h_reg = 0.f;
    if (tid < 256) {
        g_hb[0][0][bu * H_ + j0 + ju] = __float2bfloat16(0.f);
        g_hb[0][1][bu * H_ + j0 + ju] = __float2bfloat16(0.f);
    }

    unsigned want = NB;
    grid_bar(want);

    for (int t = 0; t < T_; ++t) {
        // gx prefetch for reduce phase
        float gx0 = __ldg(&g_gx[((size_t)rn * T_ + t) * G_ + gxcol]);
        float gx1 = __ldg(&g_gx[((size_t)(rn + 1) * T_ + t) * G_ + gxcol]);

        // stage this pair's 16KB chunk: contiguous 256B per thread
        {
            const uint4* hs = (const uint4*)(g_hb[t & 1][nh] + (size_t)lane * H_ + kw * 128);
            uint4 v[8];
#pragma unroll
            for (int u = 0; u < 8; ++u) v[u] = __ldcg(hs + u);
#pragma unroll
            for (int u = 0; u < 8; ++u)
                *(uint4*)(sdst + ((u * 16) ^ sx)) = v[u];
#pragma unroll
            for (int u = 0; u < 8; ++u) v[u] = __ldcg(hs + 8 + u);
#pragma unroll
            for (int u = 0; u < 8; ++u)
                *(uint4*)(sdst + (((u + 8) * 16) ^ sx)) = v[u];
        }
        asm volatile("bar.sync %0, 64;" :: "r"(1 + kw) : "memory");

        // mma: 8 k-tiles x 2 mi x 2 n-tiles x 3 terms
        float c[2][2][4];
#pragma unroll
        for (int mi = 0; mi < 2; ++mi)
#pragma unroll
            for (int nj = 0; nj < 2; ++nj)
#pragma unroll
                for (int q = 0; q < 4; ++q) c[mi][nj][q] = 0.f;

#pragma unroll
        for (int kt = 0; kt < 8; ++kt) {
            const unsigned colb = ((unsigned)(kt * 32) + bk4) ^ xb;
            unsigned bh[4], bl[4], al[4];
            ldsm4(bh, bbase + colb);
#pragma unroll
            for (int mi = 0; mi < 2; ++mi) {
                ldsm4(al, sbase + OFF_ALO + arow[mi] + ((acolk + kt * 32) ^ xa));
                mma16816(c[mi][0], wa[kt][mi], bh[0], bh[1]);
                mma16816(c[mi][1], wa[kt][mi], bh[2], bh[3]);
                mma16816(c[mi][0], al, bh[0], bh[1]);
                mma16816(c[mi][1], al, bh[2], bh[3]);
            }
            ldsm4(bl, bbase + 8192 + colb);
#pragma unroll
            for (int mi = 0; mi < 2; ++mi) {
                mma16816(c[mi][0], wa[kt][mi], bl[0], bl[1]);
                mma16816(c[mi][1], wa[kt][mi], bl[2], bl[3]);
            }
        }
        asm volatile("bar.sync %0, 64;" :: "r"(1 + kw) : "memory");

        // partials overlay this pair's chunk: [m32][n34] f32
        {
            float* part = (float*)(sm + OFF_H + kw * CHK);
#pragma unroll
            for (int mi = 0; mi < 2; ++mi)
#pragma unroll
                for (int nj = 0; nj < 2; ++nj) {
                    int m = mi * 16 + (lane >> 2);
                    int n = nh * 16 + nj * 8 + (lane & 3) * 2;
                    *(float2*)&part[m * 34 + n]       = make_float2(c[mi][nj][0], c[mi][nj][1]);
                    *(float2*)&part[(m + 8) * 34 + n] = make_float2(c[mi][nj][2], c[mi][nj][3]);
                }
        }
        __syncthreads();

        // reduce over 8 kw-partials + gx
        {
            float sx0 = gx0, sx1 = gx1;
#pragma unroll
            for (int k = 0; k < 8; ++k) {
                float2 p = *(float2*)((float*)(sm + OFF_H + k * CHK) + rm * 34 + rn);
                sx0 += p.x; sx1 += p.y;
            }
            g_s[rm * 34 + rn] = sx0;
            g_s[rm * 34 + rn + 1] = sx1;
        }
        __syncthreads();

        // pointwise update (fp32 state), threads 0..255
        if (tid < 256) {
            float fg = sigf(g_s[(0 * 8 + ju) * 34 + bu]);
            float ig = sigf(g_s[(1 * 8 + ju) * 34 + bu]);
            float og = sigf(g_s[(2 * 8 + ju) * 34 + bu]);
            float cg = tanhf(g_s[(3 * 8 + ju) * 34 + bu]);
            float cn = fg * c_reg + ig * cg;
            float hn = og * tanhf(cn);
            if (t < len_s[bu]) { c_reg = cn; h_reg = hn; }
            __nv_bfloat16 hh = __float2bfloat16(h_reg);
            __nv_bfloat16 hl = __float2bfloat16(h_reg - __bfloat162float(hh));
            int nbuf = (t & 1) ^ 1;
            g_hb[nbuf][0][bu * H_ + j0 + ju] = hh;
            g_hb[nbuf][1][bu * H_ + j0 + ju] = hl;
            outp[((size_t)bu * T_ + t) * H_ + (j0 + ju)] = h_reg;
        }

        want += NB;
        grid_bar(want);
    }
    if (tid < 256) {
        cdst[(size_t)bu * H_ + j0 + ju] = c_reg;
        hdst[(size_t)bu * H_ + j0 + ju] = h_reg;
    }
}

extern "C" void kernel_launch(void* const* d_in, const int* in_sizes, int n_in,
                              void* d_out, int out_size)
{
    const float* x    = (const float*)d_in[0];
    const void*  len  = d_in[1];
    const float* wih0 = (const float*)d_in[2];
    const float* whh0 = (const float*)d_in[3];
    const float* b0   = (const float*)d_in[4];
    const float* wih1 = (const float*)d_in[5];
    const float* whh1 = (const float*)d_in[6];
    const float* b1   = (const float*)d_in[7];
    float* out = (float*)d_out;

    void *bar_p, *out0_p, *ahi_p, *alo_p, *whi_p, *wlo_p;
    cudaGetSymbolAddress(&bar_p, g_bar);
    cudaGetSymbolAddress(&out0_p, g_out0);
    cudaGetSymbolAddress(&ahi_p, g_Ahi);
    cudaGetSymbolAddress(&alo_p, g_Alo);
    cudaGetSymbolAddress(&whi_p, g_Whi);
    cudaGetSymbolAddress(&wlo_p, g_Wlo);
    float* out0 = (float*)out0_p;
    __nv_bfloat16* Ahi = (__nv_bfloat16*)ahi_p;
    __nv_bfloat16* Alo = (__nv_bfloat16*)alo_p;
    __nv_bfloat16* Whi = (__nv_bfloat16*)whi_p;
    __nv_bfloat16* Wlo = (__nv_bfloat16*)wlo_p;

    cudaFuncSetAttribute(lstm_rec, cudaFuncAttributeMaxDynamicSharedMemorySize, REC_SMEM);
    cudaFuncSetAttribute(tc_gemm, cudaFuncAttributeMaxDynamicSharedMemorySize, TC_SMEM);

    const size_t O1 = (size_t)B_ * T_ * H_;
    float* c0dst = out + O1;
    float* c1dst = out + O1 + (size_t)B_ * H_;
    float* h0dst = out + O1 + 2 * (size_t)B_ * H_;
    float* h1dst = out + O1 + 3 * (size_t)B_ * H_;

    const int nA4 = (B_ * T_ * H_) / 4;
    const int nW4 = (G_ * H_) / 4;
    dim3 gg(G_ / 128, (B_ * T_) / 128);

    conv_split<<<nW4 / 256, 256>>>(wih0, Whi, Wlo, nW4);
    conv_split<<<nA4 / 256, 256>>>(x, Ahi, Alo, nA4);
    tc_gemm<<<gg, 256, TC_SMEM>>>(Ahi, Alo, Whi, Wlo, b0);
    cudaMemsetAsync(bar_p, 0, sizeof(unsigned), 0);
    lstm_rec<<<NB, THR, REC_SMEM>>>(whh0, len, out0, c0dst, h0dst);

    conv_split<<<nW4 / 256, 256>>>(wih1, Whi, Wlo, nW4);
    conv_split<<<nA4 / 256, 256>>>(out0, Ahi, Alo, nA4);
    tc_gemm<<<gg, 256, TC_SMEM>>>(Ahi, Alo, Whi, Wlo, b1);
    cudaMemsetAsync(bar_p, 0, sizeof(unsigned), 0);
    lstm_rec<<<NB, THR, REC_SMEM>>>(whh1, len, out, c1dst, h1dst);
}

// round 9
// speedup vs baseline: 1.1643x; 1.0252x over previous
#include <cuda_runtime.h>
#include <cuda_bf16.h>
#include <cstddef>

#define B_ 32
#define T_ 512
#define H_ 1024
#define G_ 4096
#define NB 128

__device__ float g_gx[(size_t)B_ * T_ * G_];
__device__ float g_out0[(size_t)B_ * T_ * H_];
__device__ __nv_bfloat16 g_hb[2][2][(size_t)B_ * H_];   // [buf][hi/lo][b*1024+k]
__device__ unsigned g_bars[8 * 32];                      // 8 counters, 128B apart
__device__ __nv_bfloat16 g_Ahi[(size_t)B_ * T_ * H_];
__device__ __nv_bfloat16 g_Alo[(size_t)B_ * T_ * H_];
__device__ __nv_bfloat16 g_Whi[(size_t)G_ * H_];
__device__ __nv_bfloat16 g_Wlo[(size_t)G_ * H_];

// ---------------- hi/lo bf16 split conversion ---------------------------------
__global__ __launch_bounds__(256) void conv_split(
    const float* __restrict__ s, __nv_bfloat16* __restrict__ hi,
    __nv_bfloat16* __restrict__ lo, int n4)
{
    int i = blockIdx.x * 256 + threadIdx.x;
    if (i >= n4) return;
    float4 v = ((const float4*)s)[i];
    __nv_bfloat16 h0 = __float2bfloat16(v.x), h1 = __float2bfloat16(v.y);
    __nv_bfloat16 h2 = __float2bfloat16(v.z), h3 = __float2bfloat16(v.w);
    __nv_bfloat16 l0 = __float2bfloat16(v.x - __bfloat162float(h0));
    __nv_bfloat16 l1 = __float2bfloat16(v.y - __bfloat162float(h1));
    __nv_bfloat16 l2 = __float2bfloat16(v.z - __bfloat162float(h2));
    __nv_bfloat16 l3 = __float2bfloat16(v.w - __bfloat162float(h3));
    ((__nv_bfloat162*)hi)[i * 2]     = __nv_bfloat162(h0, h1);
    ((__nv_bfloat162*)hi)[i * 2 + 1] = __nv_bfloat162(h2, h3);
    ((__nv_bfloat162*)lo)[i * 2]     = __nv_bfloat162(l0, l1);
    ((__nv_bfloat162*)lo)[i * 2 + 1] = __nv_bfloat162(l2, l3);
}

// ---------------- mma helpers --------------------------------------------------
__device__ __forceinline__ void ldsm4(unsigned* r, unsigned a) {
    asm volatile("ldmatrix.sync.aligned.m8n8.x4.shared.b16 {%0,%1,%2,%3}, [%4];"
                 : "=r"(r[0]), "=r"(r[1]), "=r"(r[2]), "=r"(r[3]) : "r"(a));
}
__device__ __forceinline__ void mma16816(float* c, const unsigned* a,
                                         unsigned b0, unsigned b1) {
    asm volatile(
        "mma.sync.aligned.m16n8k16.row.col.f32.bf16.bf16.f32 "
        "{%0,%1,%2,%3}, {%4,%5,%6,%7}, {%8,%9}, {%0,%1,%2,%3};"
        : "+f"(c[0]), "+f"(c[1]), "+f"(c[2]), "+f"(c[3])
        : "r"(a[0]), "r"(a[1]), "r"(a[2]), "r"(a[3]), "r"(b0), "r"(b1));
}
__device__ __forceinline__ void cpa(unsigned s, const void* g) {
    asm volatile("cp.async.cg.shared.global [%0], [%1], 16;" :: "r"(s), "l"(g));
}

// ---------------- tensor-core GEMM (unchanged) --------------------------------
#define SR 40
#define BUFB (128 * SR * 2)
#define OFF_AH 0
#define OFF_AL (2 * BUFB)
#define OFF_BH (4 * BUFB)
#define OFF_BL (6 * BUFB)
#define TC_SMEM (8 * BUFB)

__global__ __launch_bounds__(256, 1) void tc_gemm(
    const __nv_bfloat16* __restrict__ Ahi, const __nv_bfloat16* __restrict__ Alo,
    const __nv_bfloat16* __restrict__ Whi, const __nv_bfloat16* __restrict__ Wlo,
    const float* __restrict__ bias)
{
    extern __shared__ char sm[];
    const unsigned sbase = (unsigned)__cvta_generic_to_shared(sm);
    const int tid = threadIdx.x, lane = tid & 31, wid = tid >> 5;
    const int wm = wid & 3, wn = wid >> 2;
    const int m0 = blockIdx.y * 128, n0 = blockIdx.x * 128;

    int frow[2], fch[2];
    unsigned sA[2];
#pragma unroll
    for (int u = 0; u < 2; ++u) {
        int id = tid + 256 * u;
        frow[u] = id >> 2; fch[u] = (id & 3) * 8;
        sA[u] = (frow[u] * SR + fch[u]) * 2;
    }
    const int arow = wm * 32 + (lane & 7) + (lane & 8);
    const unsigned a_base = (arow * SR + (lane >> 4) * 8) * 2;
    const int brow = wn * 64 + (lane & 7) + (lane >> 4) * 8;
    const unsigned b_base = (brow * SR + ((lane >> 3) & 1) * 8) * 2;

    float c[2][8][4];
#pragma unroll
    for (int i = 0; i < 2; ++i)
#pragma unroll
        for (int j = 0; j < 8; ++j)
#pragma unroll
            for (int q = 0; q < 4; ++q) c[i][j][q] = 0.f;

#pragma unroll
    for (int u = 0; u < 2; ++u) {
        size_t ga = (size_t)(m0 + frow[u]) * H_ + fch[u];
        size_t gb = (size_t)(n0 + frow[u]) * H_ + fch[u];
        cpa(sbase + OFF_AH + sA[u], &Ahi[ga]);
        cpa(sbase + OFF_AL + sA[u], &Alo[ga]);
        cpa(sbase + OFF_BH + sA[u], &Whi[gb]);
        cpa(sbase + OFF_BL + sA[u], &Wlo[gb]);
    }
    asm volatile("cp.async.commit_group;");

    for (int s = 0; s < 32; ++s) {
        asm volatile("cp.async.wait_group 0;");
        __syncthreads();
        if (s + 1 < 32) {
            int k0 = (s + 1) * 32, bf = (s + 1) & 1;
#pragma unroll
            for (int u = 0; u < 2; ++u) {
                size_t ga = (size_t)(m0 + frow[u]) * H_ + k0 + fch[u];
                size_t gb = (size_t)(n0 + frow[u]) * H_ + k0 + fch[u];
                cpa(sbase + OFF_AH + bf * BUFB + sA[u], &Ahi[ga]);
                cpa(sbase + OFF_AL + bf * BUFB + sA[u], &Alo[ga]);
                cpa(sbase + OFF_BH + bf * BUFB + sA[u], &Whi[gb]);
                cpa(sbase + OFF_BL + bf * BUFB + sA[u], &Wlo[gb]);
            }
            asm volatile("cp.async.commit_group;");
        }
        const unsigned bo = (s & 1) * BUFB;
#pragma unroll
        for (int kk = 0; kk < 2; ++kk) {
            unsigned ah[2][4], al[2][4], bh[4][4], bl[4][4];
#pragma unroll
            for (int mi = 0; mi < 2; ++mi) {
                unsigned ad = sbase + bo + a_base + mi * (16 * SR * 2) + kk * 32;
                ldsm4(ah[mi], ad + OFF_AH);
                ldsm4(al[mi], ad + OFF_AL);
            }
#pragma unroll
            for (int j = 0; j < 4; ++j) {
                unsigned bd = sbase + bo + b_base + j * (16 * SR * 2) + kk * 32;
                ldsm4(bh[j], bd + OFF_BH);
                ldsm4(bl[j], bd + OFF_BL);
            }
#pragma unroll
            for (int mi = 0; mi < 2; ++mi)
#pragma unroll
                for (int j = 0; j < 4; ++j) {
                    mma16816(c[mi][2*j],   ah[mi], bh[j][0], bh[j][1]);
                    mma16816(c[mi][2*j+1], ah[mi], bh[j][2], bh[j][3]);
                    mma16816(c[mi][2*j],   ah[mi], bl[j][0], bl[j][1]);
                    mma16816(c[mi][2*j+1], ah[mi], bl[j][2], bl[j][3]);
                    mma16816(c[mi][2*j],   al[mi], bh[j][0], bh[j][1]);
                    mma16816(c[mi][2*j+1], al[mi], bh[j][2], bh[j][3]);
                }
        }
        __syncthreads();
    }
#pragma unroll
    for (int mi = 0; mi < 2; ++mi) {
        int gr = m0 + wm * 32 + mi * 16 + (lane >> 2);
#pragma unroll
        for (int ni = 0; ni < 8; ++ni) {
            int gc = n0 + wn * 64 + ni * 8 + (lane & 3) * 2;
            float2 bv = *(const float2*)&bias[gc];
            float* cc = c[mi][ni];
            *(float2*)&g_gx[(size_t)gr * G_ + gc] =
                make_float2(cc[0] + bv.x, cc[1] + bv.y);
            *(float2*)&g_gx[(size_t)(gr + 8) * G_ + gc] =
                make_float2(cc[2] + bv.x, cc[3] + bv.y);
        }
    }
}

// ---------------- persistent tensorized LSTM recurrence (R5 + fixes) ----------
__device__ __forceinline__ float sigf(float x) { return 1.0f / (1.0f + __expf(-x)); }

__device__ __forceinline__ void grid_bar(int bid, unsigned want_sum) {
    __syncthreads();
    if (threadIdx.x == 0) {
        asm volatile("red.release.gpu.global.add.u32 [%0], 1;"
                     :: "l"(&g_bars[(bid & 7) * 32]) : "memory");
        unsigned s;
        do {
            s = 0;
#pragma unroll
            for (int i = 0; i < 8; ++i) {
                unsigned v;
                asm volatile("ld.acquire.gpu.global.u32 %0, [%1];"
                             : "=r"(v) : "l"(&g_bars[i * 32]));
                s += v;
            }
        } while (s < want_sum);
    }
    __syncthreads();
}

// SMEM byte offsets (identical to R5)
#define WSTR 1032
#define OFF_WHI 0
#define OFF_WLO (32 * WSTR * 2)                // 66048
#define OFF_HS  (2 * 32 * WSTR * 2)            // 132096
#define HSTR 136
#define HS_HILO (32 * HSTR * 2)                // 8704
#define HS_BUF  (2 * HS_HILO)                  // 17408
#define OFF_RED (OFF_HS + 2 * HS_BUF)          // 166912
#define OFF_GS  (OFF_RED + 8 * 32 * 16 * 4)    // 183296
#define OFF_LEN (OFF_GS + 32 * 36 * 4)         // 187904
#define REC_SMEM (OFF_LEN + 128)               // 188032

__global__ __launch_bounds__(256, 1) void lstm_rec(
    const float* __restrict__ whh, const void* __restrict__ len_raw,
    float* __restrict__ outp, float* __restrict__ cdst, float* __restrict__ hdst)
{
    extern __shared__ char sm[];
    const unsigned sbase = (unsigned)__cvta_generic_to_shared(sm);
    float* red = (float*)(sm + OFF_RED);
    float* g_s = (float*)(sm + OFF_GS);
    int* len_s = (int*)(sm + OFF_LEN);

    const int tid = threadIdx.x, lane = tid & 31, wid = tid >> 5;
    const int bid = blockIdx.x;
    const int j0 = bid * 8;

    if (tid == 0) {
        const int* L = (const int*)len_raw;
        bool is64 = true;
        for (int i = 1; i < 32; i += 2) if (L[i] != 0) { is64 = false; break; }
        for (int b = 0; b < 32; ++b) len_s[b] = is64 ? L[2 * b] : L[b];
    }

    // stage + split W_hh slice
    {
        const int r = tid & 31;
        const int grow = (r >> 3) * 1024 + j0 + (r & 7);
        const int k0 = (tid >> 5) * 128;
        const float* src = &whh[(size_t)grow * H_ + k0];
        __nv_bfloat162* whi = (__nv_bfloat162*)(sm + OFF_WHI);
        __nv_bfloat162* wlo = (__nv_bfloat162*)(sm + OFF_WLO);
#pragma unroll
        for (int kk = 0; kk < 128; kk += 4) {
            float4 v = *(const float4*)&src[kk];
            __nv_bfloat16 h0 = __float2bfloat16(v.x), h1 = __float2bfloat16(v.y);
            __nv_bfloat16 h2 = __float2bfloat16(v.z), h3 = __float2bfloat16(v.w);
            int e = r * WSTR + k0 + kk;
            whi[e / 2]     = __nv_bfloat162(h0, h1);
            whi[e / 2 + 1] = __nv_bfloat162(h2, h3);
            wlo[e / 2]     = __nv_bfloat162(__float2bfloat16(v.x - __bfloat162float(h0)),
                                            __float2bfloat16(v.y - __bfloat162float(h1)));
            wlo[e / 2 + 1] = __nv_bfloat162(__float2bfloat16(v.z - __bfloat162float(h2)),
                                            __float2bfloat16(v.w - __bfloat162float(h3)));
        }
    }

    // warp roles
    const int kw = wid >> 1, nh = wid & 1;
    const unsigned a_off = ((lane & 7) + (lane & 8)) * (WSTR * 2) + ((lane >> 4) * 8) * 2;
    const unsigned b_off = ((nh * 16 + (lane & 7) + (lane >> 4) * 8) * HSTR
                            + ((lane >> 3) & 1) * 8) * 2;

    // h-chunk staging map
    const int shl = tid >> 7, srem = tid & 127;
    const int sb = srem >> 2, sk = (srem & 3) * 32;
    const unsigned s_dst = OFF_HS + shl * HS_HILO + (sb * HSTR + sk) * 2;

    // reduce / gx map
    const int ro = tid >> 3, bq = tid & 7, b0g = bq * 4;
    const int rnh = b0g >> 4, rnl = b0g & 15;
    const size_t ocol = (size_t)(ro >> 3) * 1024 + j0 + (ro & 7);

    // update map
    const int ju = tid & 7, bu = tid >> 3;
    float c_reg = 0.f, h_reg = 0.f;
    g_hb[0][0][bu * H_ + j0 + ju] = __float2bfloat16(0.f);
    g_hb[0][1][bu * H_ + j0 + ju] = __float2bfloat16(0.f);

    unsigned want = NB;
    grid_bar(bid, want);

    for (int t = 0; t < T_; ++t) {
        float gxv[4];
#pragma unroll
        for (int e = 0; e < 4; ++e)
            gxv[e] = __ldg(&g_gx[((size_t)(b0g + e) * T_ + t) * G_ + ocol]);

        const __nv_bfloat16* hsrc = g_hb[t & 1][shl];
        // prologue: stage chunk 0
        uint4 nxt[4];
#pragma unroll
        for (int u = 0; u < 4; ++u)
            nxt[u] = __ldcg((const uint4*)&hsrc[(size_t)sb * H_ + sk] + u);
#pragma unroll
        for (int u = 0; u < 4; ++u)
            *(uint4*)(sm + s_dst + u * 16) = nxt[u];
        __syncthreads();

        float c[2][2][4];
#pragma unroll
        for (int mi = 0; mi < 2; ++mi)
#pragma unroll
            for (int nj = 0; nj < 2; ++nj)
#pragma unroll
                for (int q = 0; q < 4; ++q) c[mi][nj][q] = 0.f;

        for (int kc = 0; kc < 8; ++kc) {
            if (kc < 7) {
#pragma unroll
                for (int u = 0; u < 4; ++u)
                    nxt[u] = __ldcg((const uint4*)&hsrc[(size_t)sb * H_ + (kc + 1) * 128 + sk] + u);
            }
            const unsigned hb_s = sbase + OFF_HS + (kc & 1) * HS_BUF;
#pragma unroll
            for (int ks = 0; ks < 2; ++ks) {
                const int kloc = kw * 32 + ks * 16;
                const int kg = kc * 128 + kloc;
                unsigned ah[2][4], al[2][4], bh[4], bl[4];
                unsigned bd = hb_s + b_off + kloc * 2;
                ldsm4(bh, bd);
                ldsm4(bl, bd + HS_HILO);
#pragma unroll
                for (int mi = 0; mi < 2; ++mi) {
                    unsigned ad = sbase + a_off + (mi * 16 * WSTR + kg) * 2;
                    ldsm4(ah[mi], ad + OFF_WHI);
                    ldsm4(al[mi], ad + OFF_WLO);
                }
#pragma unroll
                for (int mi = 0; mi < 2; ++mi)
#pragma unroll
                    for (int nj = 0; nj < 2; ++nj) {
                        mma16816(c[mi][nj], ah[mi], bh[2*nj], bh[2*nj+1]);
                        mma16816(c[mi][nj], ah[mi], bl[2*nj], bl[2*nj+1]);
                        mma16816(c[mi][nj], al[mi], bh[2*nj], bh[2*nj+1]);
                    }
            }
            if (kc < 7) {
                const unsigned nb_s = s_dst + ((kc + 1) & 1) * HS_BUF;
#pragma unroll
                for (int u = 0; u < 4; ++u)
                    *(uint4*)(sm + nb_s + u * 16) = nxt[u];
            }
            __syncthreads();
        }

#pragma unroll
        for (int mi = 0; mi < 2; ++mi)
#pragma unroll
            for (int nj = 0; nj < 2; ++nj) {
                int m = mi * 16 + (lane >> 2);
                int nl = nj * 8 + (lane & 3) * 2;
                float* rb = &red[((kw * 2 + nh) * 32) * 16];
                *(float2*)&rb[m * 16 + nl]       = make_float2(c[mi][nj][0], c[mi][nj][1]);
                *(float2*)&rb[(m + 8) * 16 + nl] = make_float2(c[mi][nj][2], c[mi][nj][3]);
            }
        __syncthreads();

        {
            float s0 = gxv[0], s1 = gxv[1], s2 = gxv[2], s3 = gxv[3];
#pragma unroll
            for (int s = 0; s < 4; ++s) {
                float4 p = *(float4*)&red[((s * 2 + rnh) * 32 + ro) * 16 + rnl];
                s0 += p.x; s1 += p.y; s2 += p.z; s3 += p.w;
            }
            *(float4*)&g_s[ro * 36 + b0g] = make_float4(s0, s1, s2, s3);
        }
        __syncthreads();

        {
            float fg = sigf(g_s[(0 * 8 + ju) * 36 + bu]);
            float ig = sigf(g_s[(1 * 8 + ju) * 36 + bu]);
            float og = sigf(g_s[(2 * 8 + ju) * 36 + bu]);
            float cg = tanhf(g_s[(3 * 8 + ju) * 36 + bu]);
            float cn = fg * c_reg + ig * cg;
            float hn = og * tanhf(cn);
            if (t < len_s[bu]) { c_reg = cn; h_reg = hn; }
            __nv_bfloat16 hh = __float2bfloat16(h_reg);
            __nv_bfloat16 hl = __float2bfloat16(h_reg - __bfloat162float(hh));
            int nbuf = (t & 1) ^ 1;
            g_hb[nbuf][0][bu * H_ + j0 + ju] = hh;
            g_hb[nbuf][1][bu * H_ + j0 + ju] = hl;
            outp[((size_t)bu * T_ + t) * H_ + (j0 + ju)] = h_reg;
        }

        want += NB;
        grid_bar(bid, want);
    }
    cdst[(size_t)bu * H_ + j0 + ju] = c_reg;
    hdst[(size_t)bu * H_ + j0 + ju] = h_reg;
}

extern "C" void kernel_launch(void* const* d_in, const int* in_sizes, int n_in,
                              void* d_out, int out_size)
{
    const float* x    = (const float*)d_in[0];
    const void*  len  = d_in[1];
    const float* wih0 = (const float*)d_in[2];
    const float* whh0 = (const float*)d_in[3];
    const float* b0   = (const float*)d_in[4];
    const float* wih1 = (const float*)d_in[5];
    const float* whh1 = (const float*)d_in[6];
    const float* b1   = (const float*)d_in[7];
    float* out = (float*)d_out;

    void *bar_p, *out0_p, *ahi_p, *alo_p, *whi_p, *wlo_p;
    cudaGetSymbolAddress(&bar_p, g_bars);
    cudaGetSymbolAddress(&out0_p, g_out0);
    cudaGetSymbolAddress(&ahi_p, g_Ahi);
    cudaGetSymbolAddress(&alo_p, g_Alo);
    cudaGetSymbolAddress(&whi_p, g_Whi);
    cudaGetSymbolAddress(&wlo_p, g_Wlo);
    float* out0 = (float*)out0_p;
    __nv_bfloat16* Ahi = (__nv_bfloat16*)ahi_p;
    __nv_bfloat16* Alo = (__nv_bfloat16*)alo_p;
    __nv_bfloat16* Whi = (__nv_bfloat16*)whi_p;
    __nv_bfloat16* Wlo = (__nv_bfloat16*)wlo_p;

    cudaFuncSetAttribute(lstm_rec, cudaFuncAttributeMaxDynamicSharedMemorySize, REC_SMEM);
    cudaFuncSetAttribute(tc_gemm, cudaFuncAttributeMaxDynamicSharedMemorySize, TC_SMEM);

    const size_t O1 = (size_t)B_ * T_ * H_;
    float* c0dst = out + O1;
    float* c1dst = out + O1 + (size_t)B_ * H_;
    float* h0dst = out + O1 + 2 * (size_t)B_ * H_;
    float* h1dst = out + O1 + 3 * (size_t)B_ * H_;

    const int nA4 = (B_ * T_ * H_) / 4;
    const int nW4 = (G_ * H_) / 4;
    dim3 gg(G_ / 128, (B_ * T_) / 128);

    conv_split<<<nW4 / 256, 256>>>(wih0, Whi, Wlo, nW4);
    conv_split<<<nA4 / 256, 256>>>(x, Ahi, Alo, nA4);
    tc_gemm<<<gg, 256, TC_SMEM>>>(Ahi, Alo, Whi, Wlo, b0);
    cudaMemsetAsync(bar_p, 0, 8 * 32 * sizeof(unsigned), 0);
    lstm_rec<<<NB, 256, REC_SMEM>>>(whh0, len, out0, c0dst, h0dst);

    conv_split<<<nW4 / 256, 256>>>(wih1, Whi, Wlo, nW4);
    conv_split<<<nA4 / 256, 256>>>(out0, Ahi, Alo, nA4);
    tc_gemm<<<gg, 256, TC_SMEM>>>(Ahi, Alo, Whi, Wlo, b1);
    cudaMemsetAsync(bar_p, 0, 8 * 32 * sizeof(unsigned), 0);
    lstm_rec<<<NB, 256, REC_SMEM>>>(whh1, len, out, c1dst, h1dst);
}

// round 10
// speedup vs baseline: 1.4005x; 1.2028x over previous
#include <cuda_runtime.h>
#include <cuda_bf16.h>
#include <cstddef>

#define B_ 32
#define T_ 512
#define H_ 1024
#define G_ 4096
#define NB 128

__device__ float g_gx[(size_t)B_ * T_ * G_];
__device__ float g_out0[(size_t)B_ * T_ * H_];
__device__ __nv_bfloat16 g_hb[2][2][(size_t)B_ * H_];   // [buf][hi/lo][b*1024+k]
__device__ unsigned g_bars[8 * 32];                      // 8 counters, 128B apart
__device__ __nv_bfloat16 g_Ahi[(size_t)B_ * T_ * H_];
__device__ __nv_bfloat16 g_Alo[(size_t)B_ * T_ * H_];
__device__ __nv_bfloat16 g_Whi[(size_t)G_ * H_];
__device__ __nv_bfloat16 g_Wlo[(size_t)G_ * H_];

// ---------------- hi/lo bf16 split conversion ---------------------------------
__global__ __launch_bounds__(256) void conv_split(
    const float* __restrict__ s, __nv_bfloat16* __restrict__ hi,
    __nv_bfloat16* __restrict__ lo, int n4)
{
    int i = blockIdx.x * 256 + threadIdx.x;
    if (i >= n4) return;
    float4 v = ((const float4*)s)[i];
    __nv_bfloat16 h0 = __float2bfloat16(v.x), h1 = __float2bfloat16(v.y);
    __nv_bfloat16 h2 = __float2bfloat16(v.z), h3 = __float2bfloat16(v.w);
    __nv_bfloat16 l0 = __float2bfloat16(v.x - __bfloat162float(h0));
    __nv_bfloat16 l1 = __float2bfloat16(v.y - __bfloat162float(h1));
    __nv_bfloat16 l2 = __float2bfloat16(v.z - __bfloat162float(h2));
    __nv_bfloat16 l3 = __float2bfloat16(v.w - __bfloat162float(h3));
    ((__nv_bfloat162*)hi)[i * 2]     = __nv_bfloat162(h0, h1);
    ((__nv_bfloat162*)hi)[i * 2 + 1] = __nv_bfloat162(h2, h3);
    ((__nv_bfloat162*)lo)[i * 2]     = __nv_bfloat162(l0, l1);
    ((__nv_bfloat162*)lo)[i * 2 + 1] = __nv_bfloat162(l2, l3);
}

// ---------------- mma helpers --------------------------------------------------
__device__ __forceinline__ void ldsm4(unsigned* r, unsigned a) {
    asm volatile("ldmatrix.sync.aligned.m8n8.x4.shared.b16 {%0,%1,%2,%3}, [%4];"
                 : "=r"(r[0]), "=r"(r[1]), "=r"(r[2]), "=r"(r[3]) : "r"(a));
}
__device__ __forceinline__ void mma16816(float* c, const unsigned* a,
                                         unsigned b0, unsigned b1) {
    asm volatile(
        "mma.sync.aligned.m16n8k16.row.col.f32.bf16.bf16.f32 "
        "{%0,%1,%2,%3}, {%4,%5,%6,%7}, {%8,%9}, {%0,%1,%2,%3};"
        : "+f"(c[0]), "+f"(c[1]), "+f"(c[2]), "+f"(c[3])
        : "r"(a[0]), "r"(a[1]), "r"(a[2]), "r"(a[3]), "r"(b0), "r"(b1));
}
__device__ __forceinline__ void cpa(unsigned s, const void* g) {
    asm volatile("cp.async.cg.shared.global [%0], [%1], 16;" :: "r"(s), "l"(g));
}

// ---------------- tensor-core GEMM (unchanged) --------------------------------
#define SR 40
#define BUFB (128 * SR * 2)
#define OFF_AH 0
#define OFF_AL (2 * BUFB)
#define OFF_BH (4 * BUFB)
#define OFF_BL (6 * BUFB)
#define TC_SMEM (8 * BUFB)

__global__ __launch_bounds__(256, 1) void tc_gemm(
    const __nv_bfloat16* __restrict__ Ahi, const __nv_bfloat16* __restrict__ Alo,
    const __nv_bfloat16* __restrict__ Whi, const __nv_bfloat16* __restrict__ Wlo,
    const float* __restrict__ bias)
{
    extern __shared__ char sm[];
    const unsigned sbase = (unsigned)__cvta_generic_to_shared(sm);
    const int tid = threadIdx.x, lane = tid & 31, wid = tid >> 5;
    const int wm = wid & 3, wn = wid >> 2;
    const int m0 = blockIdx.y * 128, n0 = blockIdx.x * 128;

    int frow[2], fch[2];
    unsigned sA[2];
#pragma unroll
    for (int u = 0; u < 2; ++u) {
        int id = tid + 256 * u;
        frow[u] = id >> 2; fch[u] = (id & 3) * 8;
        sA[u] = (frow[u] * SR + fch[u]) * 2;
    }
    const int arow = wm * 32 + (lane & 7) + (lane & 8);
    const unsigned a_base = (arow * SR + (lane >> 4) * 8) * 2;
    const int brow = wn * 64 + (lane & 7) + (lane >> 4) * 8;
    const unsigned b_base = (brow * SR + ((lane >> 3) & 1) * 8) * 2;

    float c[2][8][4];
#pragma unroll
    for (int i = 0; i < 2; ++i)
#pragma unroll
        for (int j = 0; j < 8; ++j)
#pragma unroll
            for (int q = 0; q < 4; ++q) c[i][j][q] = 0.f;

#pragma unroll
    for (int u = 0; u < 2; ++u) {
        size_t ga = (size_t)(m0 + frow[u]) * H_ + fch[u];
        size_t gb = (size_t)(n0 + frow[u]) * H_ + fch[u];
        cpa(sbase + OFF_AH + sA[u], &Ahi[ga]);
        cpa(sbase + OFF_AL + sA[u], &Alo[ga]);
        cpa(sbase + OFF_BH + sA[u], &Whi[gb]);
        cpa(sbase + OFF_BL + sA[u], &Wlo[gb]);
    }
    asm volatile("cp.async.commit_group;");

    for (int s = 0; s < 32; ++s) {
        asm volatile("cp.async.wait_group 0;");
        __syncthreads();
        if (s + 1 < 32) {
            int k0 = (s + 1) * 32, bf = (s + 1) & 1;
#pragma unroll
            for (int u = 0; u < 2; ++u) {
                size_t ga = (size_t)(m0 + frow[u]) * H_ + k0 + fch[u];
                size_t gb = (size_t)(n0 + frow[u]) * H_ + k0 + fch[u];
                cpa(sbase + OFF_AH + bf * BUFB + sA[u], &Ahi[ga]);
                cpa(sbase + OFF_AL + bf * BUFB + sA[u], &Alo[ga]);
                cpa(sbase + OFF_BH + bf * BUFB + sA[u], &Whi[gb]);
                cpa(sbase + OFF_BL + bf * BUFB + sA[u], &Wlo[gb]);
            }
            asm volatile("cp.async.commit_group;");
        }
        const unsigned bo = (s & 1) * BUFB;
#pragma unroll
        for (int kk = 0; kk < 2; ++kk) {
            unsigned ah[2][4], al[2][4], bh[4][4], bl[4][4];
#pragma unroll
            for (int mi = 0; mi < 2; ++mi) {
                unsigned ad = sbase + bo + a_base + mi * (16 * SR * 2) + kk * 32;
                ldsm4(ah[mi], ad + OFF_AH);
                ldsm4(al[mi], ad + OFF_AL);
            }
#pragma unroll
            for (int j = 0; j < 4; ++j) {
                unsigned bd = sbase + bo + b_base + j * (16 * SR * 2) + kk * 32;
                ldsm4(bh[j], bd + OFF_BH);
                ldsm4(bl[j], bd + OFF_BL);
            }
#pragma unroll
            for (int mi = 0; mi < 2; ++mi)
#pragma unroll
                for (int j = 0; j < 4; ++j) {
                    mma16816(c[mi][2*j],   ah[mi], bh[j][0], bh[j][1]);
                    mma16816(c[mi][2*j+1], ah[mi], bh[j][2], bh[j][3]);
                    mma16816(c[mi][2*j],   ah[mi], bl[j][0], bl[j][1]);
                    mma16816(c[mi][2*j+1], ah[mi], bl[j][2], bl[j][3]);
                    mma16816(c[mi][2*j],   al[mi], bh[j][0], bh[j][1]);
                    mma16816(c[mi][2*j+1], al[mi], bh[j][2], bh[j][3]);
                }
        }
        __syncthreads();
    }
#pragma unroll
    for (int mi = 0; mi < 2; ++mi) {
        int gr = m0 + wm * 32 + mi * 16 + (lane >> 2);
#pragma unroll
        for (int ni = 0; ni < 8; ++ni) {
            int gc = n0 + wn * 64 + ni * 8 + (lane & 3) * 2;
            float2 bv = *(const float2*)&bias[gc];
            float* cc = c[mi][ni];
            *(float2*)&g_gx[(size_t)gr * G_ + gc] =
                make_float2(cc[0] + bv.x, cc[1] + bv.y);
            *(float2*)&g_gx[(size_t)(gr + 8) * G_ + gc] =
                make_float2(cc[2] + bv.x, cc[3] + bv.y);
        }
    }
}

// ---------------- persistent tensorized LSTM recurrence -----------------------
__device__ __forceinline__ float sigf(float x) { return 1.0f / (1.0f + __expf(-x)); }

// arrivals spread over 8 counters; lanes 0-7 poll all 8 in PARALLEL (one warp load)
__device__ __forceinline__ void grid_bar(int bid, unsigned wantc) {
    __syncthreads();
    if (threadIdx.x < 8) {
        if (threadIdx.x == 0)
            asm volatile("red.release.gpu.global.add.u32 [%0], 1;"
                         :: "l"(&g_bars[(bid & 7) * 32]) : "memory");
        unsigned v;
        do {
            asm volatile("ld.acquire.gpu.global.u32 %0, [%1];"
                         : "=r"(v) : "l"(&g_bars[threadIdx.x * 32]));
        } while (v < wantc);
    }
    __syncthreads();
}

// SMEM byte offsets — 4 chunks of 256 k
#define WSTR 1032
#define OFF_WHI 0
#define OFF_WLO (32 * WSTR * 2)                // 66048
#define OFF_HS  (2 * 32 * WSTR * 2)            // 132096
#define HSTR 264
#define HS_HILO (32 * HSTR * 2)                // 16896
#define HS_BUF  (2 * HS_HILO)                  // 33792
#define OFF_RED (OFF_HS + 2 * HS_BUF)          // 199680
#define OFF_GS  (OFF_RED + 8 * 32 * 16 * 4)    // 216064
#define OFF_LEN (OFF_GS + 32 * 36 * 4)         // 220672
#define REC_SMEM (OFF_LEN + 128)               // 220800

__global__ __launch_bounds__(256, 1) void lstm_rec(
    const float* __restrict__ whh, const void* __restrict__ len_raw,
    float* __restrict__ outp, float* __restrict__ cdst, float* __restrict__ hdst)
{
    extern __shared__ char sm[];
    const unsigned sbase = (unsigned)__cvta_generic_to_shared(sm);
    float* red = (float*)(sm + OFF_RED);
    float* g_s = (float*)(sm + OFF_GS);
    int* len_s = (int*)(sm + OFF_LEN);

    const int tid = threadIdx.x, lane = tid & 31, wid = tid >> 5;
    const int bid = blockIdx.x;
    const int j0 = bid * 8;

    if (tid == 0) {
        const int* L = (const int*)len_raw;
        bool is64 = true;
        for (int i = 1; i < 32; i += 2) if (L[i] != 0) { is64 = false; break; }
        for (int b = 0; b < 32; ++b) len_s[b] = is64 ? L[2 * b] : L[b];
    }

    // stage + split W_hh slice
    {
        const int r = tid & 31;
        const int grow = (r >> 3) * 1024 + j0 + (r & 7);
        const int k0 = (tid >> 5) * 128;
        const float* src = &whh[(size_t)grow * H_ + k0];
        __nv_bfloat162* whi = (__nv_bfloat162*)(sm + OFF_WHI);
        __nv_bfloat162* wlo = (__nv_bfloat162*)(sm + OFF_WLO);
#pragma unroll
        for (int kk = 0; kk < 128; kk += 4) {
            float4 v = *(const float4*)&src[kk];
            __nv_bfloat16 h0 = __float2bfloat16(v.x), h1 = __float2bfloat16(v.y);
            __nv_bfloat16 h2 = __float2bfloat16(v.z), h3 = __float2bfloat16(v.w);
            int e = r * WSTR + k0 + kk;
            whi[e / 2]     = __nv_bfloat162(h0, h1);
            whi[e / 2 + 1] = __nv_bfloat162(h2, h3);
            wlo[e / 2]     = __nv_bfloat162(__float2bfloat16(v.x - __bfloat162float(h0)),
                                            __float2bfloat16(v.y - __bfloat162float(h1)));
            wlo[e / 2 + 1] = __nv_bfloat162(__float2bfloat16(v.z - __bfloat162float(h2)),
                                            __float2bfloat16(v.w - __bfloat162float(h3)));
        }
    }

    // warp roles: kw = k-slice (4), nh = n-half (2)
    const int kw = wid >> 1, nh = wid & 1;
    const unsigned a_off = ((lane & 7) + (lane & 8)) * (WSTR * 2) + ((lane >> 4) * 8) * 2;
    const unsigned b_off = ((nh * 16 + (lane & 7) + (lane >> 4) * 8) * HSTR
                            + ((lane >> 3) & 1) * 8) * 2;

    // h-chunk staging map: two 64B sub-blocks per thread (sk and sk+128)
    const int shl = tid >> 7, srem = tid & 127;
    const int sb = srem >> 2, sk = (srem & 3) * 32;
    const unsigned s_dst = OFF_HS + shl * HS_HILO + (sb * HSTR + sk) * 2;

    // reduce / gx map
    const int ro = tid >> 3, bq = tid & 7, b0g = bq * 4;
    const int rnh = b0g >> 4, rnl = b0g & 15;
    const size_t ocol = (size_t)(ro >> 3) * 1024 + j0 + (ro & 7);

    // update map
    const int ju = tid & 7, bu = tid >> 3;
    float c_reg = 0.f, h_reg = 0.f;
    g_hb[0][0][bu * H_ + j0 + ju] = __float2bfloat16(0.f);
    g_hb[0][1][bu * H_ + j0 + ju] = __float2bfloat16(0.f);

    unsigned wantc = 16;
    grid_bar(bid, wantc);

    for (int t = 0; t < T_; ++t) {
        float gxv[4];
#pragma unroll
        for (int e = 0; e < 4; ++e)
            gxv[e] = __ldg(&g_gx[((size_t)(b0g + e) * T_ + t) * G_ + ocol]);

        const __nv_bfloat16* hsrc = g_hb[t & 1][shl];
        // prologue: stage chunk 0 (two 64B groups per thread)
        uint4 nxt[8];
#pragma unroll
        for (int u = 0; u < 4; ++u) {
            nxt[u]     = __ldcg((const uint4*)&hsrc[(size_t)sb * H_ + sk] + u);
            nxt[u + 4] = __ldcg((const uint4*)&hsrc[(size_t)sb * H_ + sk + 128] + u);
        }
#pragma unroll
        for (int u = 0; u < 4; ++u) {
            *(uint4*)(sm + s_dst + u * 16)       = nxt[u];
            *(uint4*)(sm + s_dst + 256 + u * 16) = nxt[u + 4];
        }
        __syncthreads();

        float c[2][2][4];
#pragma unroll
        for (int mi = 0; mi < 2; ++mi)
#pragma unroll
            for (int nj = 0; nj < 2; ++nj)
#pragma unroll
                for (int q = 0; q < 4; ++q) c[mi][nj][q] = 0.f;

        for (int kc = 0; kc < 4; ++kc) {
            if (kc < 3) {
#pragma unroll
                for (int u = 0; u < 4; ++u) {
                    nxt[u]     = __ldcg((const uint4*)&hsrc[(size_t)sb * H_ + (kc + 1) * 256 + sk] + u);
                    nxt[u + 4] = __ldcg((const uint4*)&hsrc[(size_t)sb * H_ + (kc + 1) * 256 + sk + 128] + u);
                }
            }
            const unsigned hb_s = sbase + OFF_HS + (kc & 1) * HS_BUF;
#pragma unroll
            for (int ks = 0; ks < 4; ++ks) {
                const int kloc = kw * 64 + ks * 16;
                const int kg = kc * 256 + kloc;
                unsigned ah[2][4], al[2][4], bh[4], bl[4];
                unsigned bd = hb_s + b_off + kloc * 2;
                ldsm4(bh, bd);
                ldsm4(bl, bd + HS_HILO);
#pragma unroll
                for (int mi = 0; mi < 2; ++mi) {
                    unsigned ad = sbase + a_off + (mi * 16 * WSTR + kg) * 2;
                    ldsm4(ah[mi], ad + OFF_WHI);
                    ldsm4(al[mi], ad + OFF_WLO);
                }
#pragma unroll
                for (int mi = 0; mi < 2; ++mi)
#pragma unroll
                    for (int nj = 0; nj < 2; ++nj) {
                        mma16816(c[mi][nj], ah[mi], bh[2*nj], bh[2*nj+1]);
                        mma16816(c[mi][nj], ah[mi], bl[2*nj], bl[2*nj+1]);
                        mma16816(c[mi][nj], al[mi], bh[2*nj], bh[2*nj+1]);
                    }
            }
            if (kc < 3) {
                const unsigned nb_s = s_dst + ((kc + 1) & 1) * HS_BUF;
#pragma unroll
                for (int u = 0; u < 4; ++u) {
                    *(uint4*)(sm + nb_s + u * 16)       = nxt[u];
                    *(uint4*)(sm + nb_s + 256 + u * 16) = nxt[u + 4];
                }
                __syncthreads();
            }
        }

#pragma unroll
        for (int mi = 0; mi < 2; ++mi)
#pragma unroll
            for (int nj = 0; nj < 2; ++nj) {
                int m = mi * 16 + (lane >> 2);
                int nl = nj * 8 + (lane & 3) * 2;
                float* rb = &red[((kw * 2 + nh) * 32) * 16];
                *(float2*)&rb[m * 16 + nl]       = make_float2(c[mi][nj][0], c[mi][nj][1]);
                *(float2*)&rb[(m + 8) * 16 + nl] = make_float2(c[mi][nj][2], c[mi][nj][3]);
            }
        __syncthreads();

        {
            float s0 = gxv[0], s1 = gxv[1], s2 = gxv[2], s3 = gxv[3];
#pragma unroll
            for (int s = 0; s < 4; ++s) {
                float4 p = *(float4*)&red[((s * 2 + rnh) * 32 + ro) * 16 + rnl];
                s0 += p.x; s1 += p.y; s2 += p.z; s3 += p.w;
            }
            *(float4*)&g_s[ro * 36 + b0g] = make_float4(s0, s1, s2, s3);
        }
        __syncthreads();

        {
            float fg = sigf(g_s[(0 * 8 + ju) * 36 + bu]);
            float ig = sigf(g_s[(1 * 8 + ju) * 36 + bu]);
            float og = sigf(g_s[(2 * 8 + ju) * 36 + bu]);
            float cg = tanhf(g_s[(3 * 8 + ju) * 36 + bu]);
            float cn = fg * c_reg + ig * cg;
            float hn = og * tanhf(cn);
            if (t < len_s[bu]) { c_reg = cn; h_reg = hn; }
            __nv_bfloat16 hh = __float2bfloat16(h_reg);
            __nv_bfloat16 hl = __float2bfloat16(h_reg - __bfloat162float(hh));
            int nbuf = (t & 1) ^ 1;
            g_hb[nbuf][0][bu * H_ + j0 + ju] = hh;
            g_hb[nbuf][1][bu * H_ + j0 + ju] = hl;
            outp[((size_t)bu * T_ + t) * H_ + (j0 + ju)] = h_reg;
        }

        wantc += 16;
        grid_bar(bid, wantc);
    }
    cdst[(size_t)bu * H_ + j0 + ju] = c_reg;
    hdst[(size_t)bu * H_ + j0 + ju] = h_reg;
}

extern "C" void kernel_launch(void* const* d_in, const int* in_sizes, int n_in,
                              void* d_out, int out_size)
{
    const float* x    = (const float*)d_in[0];
    const void*  len  = d_in[1];
    const float* wih0 = (const float*)d_in[2];
    const float* whh0 = (const float*)d_in[3];
    const float* b0   = (const float*)d_in[4];
    const float* wih1 = (const float*)d_in[5];
    const float* whh1 = (const float*)d_in[6];
    const float* b1   = (const float*)d_in[7];
    float* out = (float*)d_out;

    void *bar_p, *out0_p, *ahi_p, *alo_p, *whi_p, *wlo_p;
    cudaGetSymbolAddress(&bar_p, g_bars);
    cudaGetSymbolAddress(&out0_p, g_out0);
    cudaGetSymbolAddress(&ahi_p, g_Ahi);
    cudaGetSymbolAddress(&alo_p, g_Alo);
    cudaGetSymbolAddress(&whi_p, g_Whi);
    cudaGetSymbolAddress(&wlo_p, g_Wlo);
    float* out0 = (float*)out0_p;
    __nv_bfloat16* Ahi = (__nv_bfloat16*)ahi_p;
    __nv_bfloat16* Alo = (__nv_bfloat16*)alo_p;
    __nv_bfloat16* Whi = (__nv_bfloat16*)whi_p;
    __nv_bfloat16* Wlo = (__nv_bfloat16*)wlo_p;

    cudaFuncSetAttribute(lstm_rec, cudaFuncAttributeMaxDynamicSharedMemorySize, REC_SMEM);
    cudaFuncSetAttribute(tc_gemm, cudaFuncAttributeMaxDynamicSharedMemorySize, TC_SMEM);

    const size_t O1 = (size_t)B_ * T_ * H_;
    float* c0dst = out + O1;
    float* c1dst = out + O1 + (size_t)B_ * H_;
    float* h0dst = out + O1 + 2 * (size_t)B_ * H_;
    float* h1dst = out + O1 + 3 * (size_t)B_ * H_;

    const int nA4 = (B_ * T_ * H_) / 4;
    const int nW4 = (G_ * H_) / 4;
    dim3 gg(G_ / 128, (B_ * T_) / 128);

    conv_split<<<nW4 / 256, 256>>>(wih0, Whi, Wlo, nW4);
    conv_split<<<nA4 / 256, 256>>>(x, Ahi, Alo, nA4);
    tc_gemm<<<gg, 256, TC_SMEM>>>(Ahi, Alo, Whi, Wlo, b0);
    cudaMemsetAsync(bar_p, 0, 8 * 32 * sizeof(unsigned), 0);
    lstm_rec<<<NB, 256, REC_SMEM>>>(whh0, len, out0, c0dst, h0dst);

    conv_split<<<nW4 / 256, 256>>>(wih1, Whi, Wlo, nW4);
    conv_split<<<nA4 / 256, 256>>>(out0, Ahi, Alo, nA4);
    tc_gemm<<<gg, 256, TC_SMEM>>>(Ahi, Alo, Whi, Wlo, b1);
    cudaMemsetAsync(bar_p, 0, 8 * 32 * sizeof(unsigned), 0);
    lstm_rec<<<NB, 256, REC_SMEM>>>(whh1, len, out, c1dst, h1dst);
}